// round 4
// baseline (speedup 1.0000x reference)
#include <cuda_runtime.h>
#include <math.h>

// iDDPMPrecond: (c_skip=1, c_out=-s, c_in=1/sqrt(s^2+1), c_noise=M-1-argmin_j|s-u_j|)
//
// Closed form: recurrence telescopes to 1+u[j]^2 = A/alpha_bar(j), A=alpha_bar(M),
// alpha_bar(j)=sin^2(c*j), c=pi/(2*M*(1+C2)). Invert analytically:
//   j_real = asin(sqrtA * rsqrt(1+s^2)) / c   (reuses c_in), index error ~0.005,
// then exact argmin over +/-1 window of the real u table (first-index ties).
//
// 4 elements/thread (float4 sigma load, 4 independent chains) -> 128 blocks x 128
// threads = single wave on 148 SMs, no wave-transition penalty, ILP-4 latency hiding.

__global__ __launch_bounds__(128)
void precond_kernel(const float4* __restrict__ sigma4,
                    const float* __restrict__ u,
                    float* __restrict__ out,
                    int B, int M, int skip_count,
                    float sqrtA, float inv_c)
{
    const int t   = blockIdx.x * blockDim.x + threadIdx.x;   // 0 .. B/4-1
    const int nth = gridDim.x * blockDim.x;

    // c_skip region (skip_count elements of 1.0f; skip=1 or skip=B both fine)
    for (int i = t; i < skip_count; i += nth) out[i] = 1.0f;

    const int i0 = 4 * t;
    if (i0 >= B) return;

    float4 sv = sigma4[t];
    float s[4] = {sv.x, sv.y, sv.z, sv.w};

    float* __restrict__ o_out   = out + skip_count;
    float* __restrict__ o_in    = out + skip_count + B;
    float* __restrict__ o_noise = out + skip_count + 2 * B;

    #pragma unroll
    for (int k = 0; k < 4; k++) {
        float sk = s[k];
        float ci = rsqrtf(fmaf(sk, sk, 1.0f));       // c_in

        // Analytic candidate index
        float jf = asinf(sqrtA * ci) * inv_c;
        int jc = __float2int_rn(jf);
        if (jc < 1)     jc = 1;
        if (jc > M - 1) jc = M - 1;

        // Exact argmin over [jc-1, jc+1]; independent cached loads.
        float d0 = fabsf(sk - __ldg(&u[jc - 1]));
        float d1 = fabsf(sk - __ldg(&u[jc]));
        float d2 = fabsf(sk - __ldg(&u[jc + 1]));

        int   best_j = jc - 1;
        float best_d = d0;
        if (d1 < best_d) { best_d = d1; best_j = jc; }
        if (d2 < best_d) {              best_j = jc + 1; }

        o_out[i0 + k]   = -sk;
        o_in[i0 + k]    = ci;
        o_noise[i0 + k] = (float)(M - 1 - best_j);
    }
}

extern "C" void kernel_launch(void* const* d_in, const int* in_sizes, int n_in,
                              void* d_out, int out_size)
{
    // inputs per metadata order: x (unused), sigma, u, M
    const float* sigma = (const float*)d_in[1];
    const float* u     = (const float*)d_in[2];
    const int B  = in_sizes[1];
    const int nU = in_sizes[2];
    const int M  = nU - 1;

    // Flattened tuple layout: [c_skip (skip elems)] [c_out B] [c_in B] [c_noise B]
    int skip = out_size - 3 * B;
    if (skip < 0) skip = 0;

    const double C2    = 0.008;
    const double c     = 3.14159265358979323846 * 0.5 / ((double)M * (1.0 + C2));
    const float  sqrtA = (float)sin(c * (double)M);   // sqrt(alpha_bar(M))
    const float  inv_c = (float)(1.0 / c);

    const int threads = 128;
    const int nThreadsTotal = (B + 3) / 4;
    const int blocks = (nThreadsTotal + threads - 1) / threads;   // 128 for B=65536
    precond_kernel<<<blocks, threads>>>((const float4*)sigma, u, (float*)d_out,
                                        B, M, skip, sqrtA, inv_c);
}